// round 10
// baseline (speedup 1.0000x reference)
#include <cuda_runtime.h>
#include <math.h>

#define T_STEPS 100
#define MDIM 16
#define NDIM 16
#define H1D  2560
#define H2D  1024
#define HIDD 5120
#define NBLK 296
#define NTHR 256
#define NWARP (NBLK * (NTHR/32))     // 2368 warps

#define NU_IH 15360                  // Wih rows (fp32), 2560 weights each
#define NU_HH 30720                  // Whh half-rows (int24), 2560 weights each
#define NU_B  (NU_IH + NU_HH)        // 46080 uniform phase-B units
#define NU_C  2048                   // W2 half-rows (fp32)

// ---------------- persistent device state ----------------
__device__ float g_l1[H1D];
__device__ float g_hbuf[2][HIDD];
__device__ float g_l2[H2D];
__device__ float g_KG[MDIM * NDIM];
__device__ float g_m1x[2][MDIM];
__device__ float g_m1y[2][NDIM];
__device__ float g_spp[2][MDIM];
__device__ unsigned g_count;
__device__ volatile unsigned g_gen;
__device__ unsigned g_cnt[HIDD];     // monotonic: 9 arrivals / element / step
__device__ unsigned g_cnt2[H2D];     // monotonic: 2 arrivals / row / step
__device__ float g_pih[NU_IH];       // partial slots (ih rows, full dot)
__device__ float g_phh[NU_HH];       // partial slots (hh half-rows, unscaled)
__device__ float g_pc[NU_C];         // partial slots (W2 half-rows)

// Whh quantized: w ~= S_hh[j*3+g] * (hi + lo/256); layout row = j*3+g
// statics ~236 MB, under the proven-loadable cap
__device__ short       Whh_hi[(size_t)HIDD * 3 * HIDD];
__device__ signed char Whh_lo[(size_t)HIDD * 3 * HIDD];
__device__ float       S_hh[HIDD * 3];

// ---------------- quantize + repack Whh (r7-proven) ----------------
__global__ void quant_hh_kernel(const float* __restrict__ src) {
    const int j = blockIdx.x, g = blockIdx.y;
    const float4* s = (const float4*)(src + ((size_t)g * HIDD + j) * HIDD);
    const size_t drow = ((size_t)j * 3 + g) * HIDD;
    __shared__ float red[256];
    float mx = 0.f;
    for (int k = threadIdx.x; k < HIDD / 4; k += 256) {
        float4 v = s[k];
        mx = fmaxf(mx, fmaxf(fmaxf(fabsf(v.x), fabsf(v.y)), fmaxf(fabsf(v.z), fabsf(v.w))));
    }
    red[threadIdx.x] = mx;
    __syncthreads();
    for (int o = 128; o > 0; o >>= 1) {
        if (threadIdx.x < o) red[threadIdx.x] = fmaxf(red[threadIdx.x], red[threadIdx.x + o]);
        __syncthreads();
    }
    float m = red[0];
    float sc  = (m > 0.f) ? m / 32767.0f : 1.0f;
    float inv = (m > 0.f) ? 32767.0f / m : 0.0f;
    if (threadIdx.x == 0) S_hh[j * 3 + g] = sc;

    uint4* hrow = (uint4*)(Whh_hi + drow);
    uint2* lrow = (uint2*)(Whh_lo + drow);
    for (int k8 = threadIdx.x; k8 < HIDD / 8; k8 += 256) {
        float4 a = s[2 * k8], b = s[2 * k8 + 1];
        float f[8] = {a.x, a.y, a.z, a.w, b.x, b.y, b.z, b.w};
        unsigned hs[8], ls[8];
#pragma unroll
        for (int i = 0; i < 8; ++i) {
            float ff = f[i] * inv;
            float hq = rintf(ff);
            float d  = (ff - hq) * 256.0f;
            float lq = fminf(fmaxf(rintf(d), -128.0f), 127.0f);
            hs[i] = (unsigned)(unsigned short)(short)hq;
            ls[i] = (unsigned)(unsigned char)(signed char)lq;
        }
        uint4 hv;
        hv.x = hs[0] | (hs[1] << 16);
        hv.y = hs[2] | (hs[3] << 16);
        hv.z = hs[4] | (hs[5] << 16);
        hv.w = hs[6] | (hs[7] << 16);
        uint2 lv;
        lv.x = ls[0] | (ls[1] << 8) | (ls[2] << 16) | (ls[3] << 24);
        lv.y = ls[4] | (ls[5] << 8) | (ls[6] << 16) | (ls[7] << 24);
        hrow[k8] = hv;
        lrow[k8] = lv;
    }
}

__global__ void init_kernel(const float* __restrict__ h0) {
    int i = blockIdx.x * blockDim.x + threadIdx.x;
    if (i < HIDD) { g_hbuf[0][i] = h0[i]; g_cnt[i] = 0u; }
    if (i < H2D) g_cnt2[i] = 0u;
    if (i == 0) { g_count = 0; g_gen = 0; }
}

// ---------------- grid-wide spin barrier (r1/r7-proven) ----------------
__device__ __forceinline__ void gsync(unsigned target) {
    __syncthreads();
    if (threadIdx.x == 0) {
        __threadfence();
        if (atomicAdd(&g_count, 1u) == gridDim.x - 1) {
            atomicExch(&g_count, 0u);
            __threadfence();
            g_gen = target;
        } else {
            while (g_gen < target) { __nanosleep(64); }
        }
        __threadfence();
    }
    __syncthreads();
}

__device__ __forceinline__ float wredsum(float v) {
#pragma unroll
    for (int o = 16; o > 0; o >>= 1) v += __shfl_xor_sync(0xffffffffu, v, o);
    return v;
}

__device__ __forceinline__ float sigmoidf_(float x) {
    return 1.0f / (1.0f + __expf(-x));
}

// decode 8 quantized weights (int16 hi + int8 lo, unscaled) . 8 x values
__device__ __forceinline__ float dec8(uint4 h, uint2 l, float4 x0, float4 x1) {
    const float R = 0.00390625f;   // 1/256
    short2 h0 = *(short2*)&h.x; short2 h1 = *(short2*)&h.y;
    short2 h2 = *(short2*)&h.z; short2 h3 = *(short2*)&h.w;
    int la = (int)l.x, lb = (int)l.y;
    float w0 = fmaf((float)(signed char)(la),       R, (float)h0.x);
    float w1 = fmaf((float)(signed char)(la >> 8),  R, (float)h0.y);
    float w2 = fmaf((float)(signed char)(la >> 16), R, (float)h1.x);
    float w3 = fmaf((float)(la >> 24),              R, (float)h1.y);
    float w4 = fmaf((float)(signed char)(lb),       R, (float)h2.x);
    float w5 = fmaf((float)(signed char)(lb >> 8),  R, (float)h2.y);
    float w6 = fmaf((float)(signed char)(lb >> 16), R, (float)h3.x);
    float w7 = fmaf((float)(lb >> 24),              R, (float)h3.y);
    float acc = w0 * x0.x;
    acc = fmaf(w1, x0.y, acc);
    acc = fmaf(w2, x0.z, acc);
    acc = fmaf(w3, x0.w, acc);
    acc = fmaf(w4, x1.x, acc);
    acc = fmaf(w5, x1.y, acc);
    acc = fmaf(w6, x1.z, acc);
    acc = fmaf(w7, x1.w, acc);
    return acc;
}

// 9th-arriver GRU gate combine for hidden element j
__device__ __forceinline__ void combine_gru(int j, float hold_j, float* __restrict__ hnew,
                                            const float* __restrict__ bih,
                                            const float* __restrict__ bhh) {
    __threadfence();   // acquire: order partial reads after the counter observation
    float ir  = __ldcg(&g_pih[j]);
    float iz  = __ldcg(&g_pih[HIDD + j]);
    float in_ = __ldcg(&g_pih[2 * HIDD + j]);
    float hr  = (__ldcg(&g_phh[2 * j])              + __ldcg(&g_phh[2 * j + 1]))              * S_hh[j * 3 + 0];
    float hz  = (__ldcg(&g_phh[2 * (HIDD + j)])     + __ldcg(&g_phh[2 * (HIDD + j) + 1]))     * S_hh[j * 3 + 1];
    float hn  = (__ldcg(&g_phh[2 * (2 * HIDD + j)]) + __ldcg(&g_phh[2 * (2 * HIDD + j) + 1])) * S_hh[j * 3 + 2];
    float r  = sigmoidf_(ir + bih[j]            + hr + bhh[j]);
    float z  = sigmoidf_(iz + bih[HIDD + j]     + hz + bhh[HIDD + j]);
    float nn = tanhf   (in_ + bih[2 * HIDD + j] + r * (hn + bhh[2 * HIDD + j]));
    hnew[j] = (1.0f - z) * nn + z * hold_j;
}

__global__ void __launch_bounds__(NTHR, 2)
knet_kernel(const float* __restrict__ y,  const float* __restrict__ F,
            const float* __restrict__ Hm, const float* __restrict__ m1_0,
            const float* __restrict__ W1, const float* __restrict__ b1,
            const float* __restrict__ Wih, const float* __restrict__ bih,
            const float* __restrict__ bhh,
            const float* __restrict__ W2, const float* __restrict__ b2,
            const float* __restrict__ W3, const float* __restrict__ b3,
            float* __restrict__ out)
{
    const int tid  = threadIdx.x;
    const int lane = tid & 31;
    const int wid  = blockIdx.x * (NTHR / 32) + (tid >> 5);  // 0..2367
    unsigned lg = 0;

    // contiguous unit chunk for this warp (phase B)
    const int ub0 = (int)(((long long)wid       * NU_B) / NWARP);
    const int ub1 = (int)(((long long)(wid + 1) * NU_B) / NWARP);

    __shared__ float s_post[16], s_spold[16], s_m1x[16], s_spnew[16];
    __shared__ float s_d[16], s_e[16], s_kin[32], s_nrm[2];

    for (int t = 0; t < T_STEPS; ++t) {
        const int cur = t & 1, prev = cur ^ 1;

        // ================= Phase A: post update + state + kin + l1 ==========
        if (tid < 16) {
            float p, sp;
            if (t == 0) {
                p = m1_0[tid]; sp = m1_0[tid];
            } else {
                float acc = g_m1x[prev][tid];
#pragma unroll
                for (int k = 0; k < 16; ++k)
                    acc += g_KG[tid * 16 + k] * (y[k * T_STEPS + (t - 1)] - g_m1y[prev][k]);
                p  = acc;
                sp = g_spp[prev][tid];
                if (blockIdx.x == 0) out[tid * T_STEPS + (t - 1)] = p;
            }
            s_post[tid] = p; s_spold[tid] = sp;
        }
        __syncthreads();
        if (tid < 16) {
            float mx = 0.f, sn = 0.f;
#pragma unroll
            for (int k = 0; k < 16; ++k) {
                float f = F[tid * 16 + k];
                mx += f * s_post[k];
                sn += f * s_spold[k];
            }
            s_m1x[tid] = mx; s_spnew[tid] = sn;
        }
        __syncthreads();
        if (tid < 16) {
            float my = 0.f, ob = 0.f;
#pragma unroll
            for (int k = 0; k < 16; ++k) {
                float h = Hm[tid * 16 + k];
                my += h * s_m1x[k];
                ob += h * s_spnew[k];
            }
            s_d[tid] = s_post[tid] - s_spold[tid];
            s_e[tid] = y[tid * T_STEPS + t] - ob;
            if (blockIdx.x == 0) {
                g_m1x[cur][tid] = s_m1x[tid];
                g_m1y[cur][tid] = my;
                g_spp[cur][tid] = s_spnew[tid];
            }
        }
        __syncthreads();
        if (tid == 0) {
            float nd = 0.f, ne = 0.f;
#pragma unroll
            for (int k = 0; k < 16; ++k) { nd += s_d[k] * s_d[k]; ne += s_e[k] * s_e[k]; }
            s_nrm[0] = fmaxf(sqrtf(nd), 1e-12f);
            s_nrm[1] = fmaxf(sqrtf(ne), 1e-12f);
        }
        __syncthreads();
        if (tid < 32)
            s_kin[tid] = (tid < 16) ? s_d[tid] / s_nrm[0] : s_e[tid - 16] / s_nrm[1];
        __syncthreads();

        // l1 = relu(W1 @ kin + b1): warp-per-row, <=2 rows per warp
        for (int row = wid; row < H1D; row += NWARP) {
            float v = W1[row * 32 + lane] * s_kin[lane];
            v = wredsum(v);
            if (lane == 0) g_l1[row] = fmaxf(v + b1[row], 0.0f);
        }
        ++lg; gsync(lg);

        // ================= Phase B: uniform units + arrival combine =========
        {
            const float*  hold = g_hbuf[cur];
            float*        hnew = g_hbuf[prev];
            const float4* l1v  = (const float4*)g_l1;
            const unsigned trig = 9u * (unsigned)t + 8u;

            for (int u = ub0; u < ub1; ++u) {
                if (u < NU_IH) {
                    // Wih row u = g*HIDD + j (fp32), dot with l1 (2560 weights)
                    const int j = u % HIDD;                    // HIDD NOT pow2 -- real mod
                    const float4* w = (const float4*)(Wih + (size_t)u * H1D);
                    float acc = 0.f;
#pragma unroll 4
                    for (int k = lane; k < H1D / 4; k += 32) {
                        float4 a = w[k]; float4 x = l1v[k];
                        acc += a.x * x.x + a.y * x.y + a.z * x.z + a.w * x.w;
                    }
                    acc = wredsum(acc);
                    if (lane == 0) {
                        __stcg(&g_pih[u], acc);
                        __threadfence();
                        if (atomicAdd(&g_cnt[j], 1u) == trig)
                            combine_gru(j, hold[j], hnew, bih, bhh);
                    }
                } else {
                    // Whh half-row: v = 2*r+half, source row r = g*HIDD + j
                    const int v = u - NU_IH;
                    const int half = v & 1;
                    const int r = v >> 1;
                    const int j  = r % HIDD;                   // real mod
                    const int gg = r / HIDD;
                    const size_t qrow = ((size_t)j * 3 + gg) * HIDD + (size_t)half * 2560;
                    const uint4* hp = (const uint4*)(Whh_hi + qrow);
                    const uint2* lp = (const uint2*)(Whh_lo + qrow);
                    const float4* xv = (const float4*)(hold + half * 2560);
                    float acc = 0.f;
#pragma unroll 2
                    for (int k = lane; k < 2560 / 8; k += 32) {
                        float4 x0 = xv[2 * k], x1 = xv[2 * k + 1];
                        acc += dec8(hp[k], lp[k], x0, x1);
                    }
                    acc = wredsum(acc);
                    if (lane == 0) {
                        __stcg(&g_phh[v], acc);
                        __threadfence();
                        if (atomicAdd(&g_cnt[j], 1u) == trig)
                            combine_gru(j, hold[j], hnew, bih, bhh);
                    }
                }
            }
        }
        ++lg; gsync(lg);

        // ================= Phase C: l2 = relu(W2 @ h_new + b2) ==============
        if (wid < NU_C) {
            const int u = wid;
            const int half = u & 1;
            const int r = u >> 1;
            const float4* hvn = (const float4*)(g_hbuf[prev] + half * 2560);
            const float4* w   = (const float4*)(W2 + (size_t)r * HIDD + (size_t)half * 2560);
            float acc = 0.f;
#pragma unroll 4
            for (int k = lane; k < 2560 / 4; k += 32) {
                float4 a = w[k]; float4 x = hvn[k];
                acc += a.x * x.x + a.y * x.y + a.z * x.z + a.w * x.w;
            }
            acc = wredsum(acc);
            if (lane == 0) {
                __stcg(&g_pc[u], acc);
                __threadfence();
                if (atomicAdd(&g_cnt2[r], 1u) == 2u * (unsigned)t + 1u) {
                    __threadfence();
                    float v2 = __ldcg(&g_pc[2 * r]) + __ldcg(&g_pc[2 * r + 1]);
                    g_l2[r] = fmaxf(v2 + b2[r], 0.0f);
                }
            }
        }
        ++lg; gsync(lg);

        // ================= Phase D: KG = W3 @ l2 + b3 =======================
        if (wid < MDIM * NDIM) {
            const float4* lv = (const float4*)g_l2;
            const float4* w  = (const float4*)(W3 + (size_t)wid * H2D);
            float acc = 0.f;
#pragma unroll
            for (int k = lane; k < H2D / 4; k += 32) {
                float4 a = w[k]; float4 x = lv[k];
                acc += a.x * x.x + a.y * x.y + a.z * x.z + a.w * x.w;
            }
            acc = wredsum(acc);
            if (lane == 0) g_KG[wid] = acc + b3[wid];
        }
        ++lg; gsync(lg);
    }

    // ---- final output column (post update of step T-1) ----
    if (blockIdx.x == 0 && tid < 16) {
        const int pl = (T_STEPS - 1) & 1;
        float acc = g_m1x[pl][tid];
#pragma unroll
        for (int k = 0; k < 16; ++k)
            acc += g_KG[tid * 16 + k] * (y[k * T_STEPS + (T_STEPS - 1)] - g_m1y[pl][k]);
        out[tid * T_STEPS + (T_STEPS - 1)] = acc;
    }
}

extern "C" void kernel_launch(void* const* d_in, const int* in_sizes, int n_in,
                              void* d_out, int out_size) {
    const float* y    = (const float*)d_in[0];
    const float* F    = (const float*)d_in[1];
    const float* Hm   = (const float*)d_in[2];
    const float* m1_0 = (const float*)d_in[3];
    const float* h0   = (const float*)d_in[4];
    const float* W1   = (const float*)d_in[5];
    const float* b1   = (const float*)d_in[6];
    const float* Wih  = (const float*)d_in[7];
    const float* bih  = (const float*)d_in[8];
    const float* Whh  = (const float*)d_in[9];
    const float* bhh  = (const float*)d_in[10];
    const float* W2   = (const float*)d_in[11];
    const float* b2   = (const float*)d_in[12];
    const float* W3   = (const float*)d_in[13];
    const float* b3   = (const float*)d_in[14];
    float* out = (float*)d_out;

    quant_hh_kernel<<<dim3(HIDD, 3), 256>>>(Whh);
    init_kernel<<<20, 256>>>(h0);
    knet_kernel<<<NBLK, NTHR>>>(y, F, Hm, m1_0, W1, b1, Wih, bih,
                                bhh, W2, b2, W3, b3, out);
}

// round 11
// speedup vs baseline: 1.2668x; 1.2668x over previous
#include <cuda_runtime.h>
#include <math.h>

#define T_STEPS 100
#define MDIM 16
#define NDIM 16
#define H1D  2560
#define H2D  1024
#define HIDD 5120
#define NBLK 444
#define NTHR 256
#define NWARP (NBLK * (NTHR/32))     // 3552 warps

#define NROW 15360                   // rows per weight matrix (3*HIDD)
#define COST_TOT (NROW * 5)          // ih rows cost 2, hh rows cost 3

// ---------------- persistent device state ----------------
__device__ float g_l1[H1D];
__device__ float g_hbuf[2][HIDD];
__device__ float g_l2[H2D];
__device__ float g_KG[MDIM * NDIM];
__device__ float g_m1x[2][MDIM];
__device__ float g_m1y[2][NDIM];
__device__ float g_spp[2][MDIM];
__device__ float g_pih[NROW];        // full-row ih partial dots
__device__ float g_phh[NROW];        // full-row hh partial dots (unscaled)
__device__ unsigned g_count;
__device__ volatile unsigned g_gen;

// Whh quantized: w ~= S_hh[j*3+g] * (hi + lo/256); row = j*3+g  (~236 MB statics)
__device__ short       Whh_hi[(size_t)HIDD * 3 * HIDD];
__device__ signed char Whh_lo[(size_t)HIDD * 3 * HIDD];
__device__ float       S_hh[HIDD * 3];

__global__ void init_kernel(const float* __restrict__ h0) {
    int i = blockIdx.x * blockDim.x + threadIdx.x;
    if (i < HIDD) g_hbuf[0][i] = h0[i];
    if (i == 0) { g_count = 0; g_gen = 0; }
}

// ---------------- grid-wide spin barrier (central; all-thread fence) ----
__device__ __forceinline__ void gsync(unsigned target) {
    __threadfence();                 // every thread publishes its stores
    __syncthreads();
    if (threadIdx.x == 0) {
        if (atomicAdd(&g_count, 1u) == gridDim.x - 1) {
            atomicExch(&g_count, 0u);
            __threadfence();
            g_gen = target;
        } else {
            while (g_gen < target) { __nanosleep(64); }
        }
        __threadfence();
    }
    __syncthreads();
}

__device__ __forceinline__ float wredsum(float v) {
#pragma unroll
    for (int o = 16; o > 0; o >>= 1) v += __shfl_xor_sync(0xffffffffu, v, o);
    return v;
}

__device__ __forceinline__ float wredmax(float v) {
#pragma unroll
    for (int o = 16; o > 0; o >>= 1) v = fmaxf(v, __shfl_xor_sync(0xffffffffu, v, o));
    return v;
}

__device__ __forceinline__ float sigmoidf_(float x) {
    return 1.0f / (1.0f + __expf(-x));
}

// decode 8 quantized weights (int16 hi + int8 lo, unscaled) . 8 x values
__device__ __forceinline__ float dec8(uint4 h, uint2 l, float4 x0, float4 x1) {
    const float R = 0.00390625f;   // 1/256
    short2 h0 = *(short2*)&h.x; short2 h1 = *(short2*)&h.y;
    short2 h2 = *(short2*)&h.z; short2 h3 = *(short2*)&h.w;
    int la = (int)l.x, lb = (int)l.y;
    float w0 = fmaf((float)(signed char)(la),       R, (float)h0.x);
    float w1 = fmaf((float)(signed char)(la >> 8),  R, (float)h0.y);
    float w2 = fmaf((float)(signed char)(la >> 16), R, (float)h1.x);
    float w3 = fmaf((float)(la >> 24),              R, (float)h1.y);
    float w4 = fmaf((float)(signed char)(lb),       R, (float)h2.x);
    float w5 = fmaf((float)(signed char)(lb >> 8),  R, (float)h2.y);
    float w6 = fmaf((float)(signed char)(lb >> 16), R, (float)h3.x);
    float w7 = fmaf((float)(lb >> 24),              R, (float)h3.y);
    float acc = w0 * x0.x;
    acc = fmaf(w1, x0.y, acc);
    acc = fmaf(w2, x0.z, acc);
    acc = fmaf(w3, x0.w, acc);
    acc = fmaf(w4, x1.x, acc);
    acc = fmaf(w5, x1.y, acc);
    acc = fmaf(w6, x1.z, acc);
    acc = fmaf(w7, x1.w, acc);
    return acc;
}

// unit cost prefix: ih unit u (u<NROW) starts at 2u; hh unit starts at 2*NROW+3*(u-NROW)
__device__ __forceinline__ long long cost_start(int u) {
    return (u < NROW) ? 2LL * u : 2LL * NROW + 3LL * (u - NROW);
}
__device__ __forceinline__ int first_unit(long long c) {
    if (c <= 2LL * NROW) return (int)((c + 1) / 2);
    return NROW + (int)((c - 2LL * NROW + 2) / 3);
}

__global__ void __launch_bounds__(NTHR, 3)
knet_kernel(const float* __restrict__ y,  const float* __restrict__ F,
            const float* __restrict__ Hm, const float* __restrict__ m1_0,
            const float* __restrict__ W1, const float* __restrict__ b1,
            const float* __restrict__ Wih, const float* __restrict__ bih,
            const float* __restrict__ Whh, const float* __restrict__ bhh,
            const float* __restrict__ W2, const float* __restrict__ b2,
            const float* __restrict__ W3, const float* __restrict__ b3,
            float* __restrict__ out)
{
    const int tid  = threadIdx.x;
    const int lane = tid & 31;
    const int wid  = blockIdx.x * (NTHR / 32) + (tid >> 5);  // 0..3551
    unsigned lg = 0;

    // cost-weighted unit range for this warp (phase B1)
    const long long c0 = (long long)wid * COST_TOT / NWARP;
    const long long c1 = (long long)(wid + 1) * COST_TOT / NWARP;
    const int u_first = first_unit(c0);

    __shared__ float s_post[16], s_spold[16], s_m1x[16], s_spnew[16];
    __shared__ float s_d[16], s_e[16], s_kin[32], s_nrm[2];

    // ============ PROLOGUE: quantize+repack Whh (warp per row) ============
    for (int r = wid; r < NROW; r += NWARP) {
        const int g = r / HIDD, j = r % HIDD;
        const float4* s = (const float4*)(Whh + (size_t)r * HIDD);   // 1280 float4
        float mx = 0.f;
        for (int k = lane; k < HIDD / 4; k += 32) {
            float4 v = s[k];
            mx = fmaxf(mx, fmaxf(fmaxf(fabsf(v.x), fabsf(v.y)), fmaxf(fabsf(v.z), fabsf(v.w))));
        }
        mx = wredmax(mx);
        float sc  = (mx > 0.f) ? mx / 32767.0f : 1.0f;
        float inv = (mx > 0.f) ? 32767.0f / mx : 0.0f;
        if (lane == 0) S_hh[j * 3 + g] = sc;
        const size_t drow = ((size_t)j * 3 + g) * HIDD;
        uint4* hrow = (uint4*)(Whh_hi + drow);
        uint2* lrow = (uint2*)(Whh_lo + drow);
        for (int k8 = lane; k8 < HIDD / 8; k8 += 32) {
            float4 a = s[2 * k8], b = s[2 * k8 + 1];
            float f[8] = {a.x, a.y, a.z, a.w, b.x, b.y, b.z, b.w};
            unsigned hs[8], ls[8];
#pragma unroll
            for (int i = 0; i < 8; ++i) {
                float ff = f[i] * inv;
                float hq = rintf(ff);
                float d  = (ff - hq) * 256.0f;
                float lq = fminf(fmaxf(rintf(d), -128.0f), 127.0f);
                hs[i] = (unsigned)(unsigned short)(short)hq;
                ls[i] = (unsigned)(unsigned char)(signed char)lq;
            }
            uint4 hv;
            hv.x = hs[0] | (hs[1] << 16);
            hv.y = hs[2] | (hs[3] << 16);
            hv.z = hs[4] | (hs[5] << 16);
            hv.w = hs[6] | (hs[7] << 16);
            uint2 lv;
            lv.x = ls[0] | (ls[1] << 8) | (ls[2] << 16) | (ls[3] << 24);
            lv.y = ls[4] | (ls[5] << 8) | (ls[6] << 16) | (ls[7] << 24);
            hrow[k8] = hv;
            lrow[k8] = lv;
        }
    }
    ++lg; gsync(lg);

    for (int t = 0; t < T_STEPS; ++t) {
        const int cur = t & 1, prev = cur ^ 1;

        // ================= Phase A: post update + state + kin + l1 ==========
        if (tid < 16) {
            float p, sp;
            if (t == 0) {
                p = m1_0[tid]; sp = m1_0[tid];
            } else {
                float acc = g_m1x[prev][tid];
#pragma unroll
                for (int k = 0; k < 16; ++k)
                    acc += g_KG[tid * 16 + k] * (y[k * T_STEPS + (t - 1)] - g_m1y[prev][k]);
                p  = acc;
                sp = g_spp[prev][tid];
                if (blockIdx.x == 0) out[tid * T_STEPS + (t - 1)] = p;
            }
            s_post[tid] = p; s_spold[tid] = sp;
        }
        __syncthreads();
        if (tid < 16) {
            float mx = 0.f, sn = 0.f;
#pragma unroll
            for (int k = 0; k < 16; ++k) {
                float f = F[tid * 16 + k];
                mx += f * s_post[k];
                sn += f * s_spold[k];
            }
            s_m1x[tid] = mx; s_spnew[tid] = sn;
        }
        __syncthreads();
        if (tid < 16) {
            float my = 0.f, ob = 0.f;
#pragma unroll
            for (int k = 0; k < 16; ++k) {
                float h = Hm[tid * 16 + k];
                my += h * s_m1x[k];
                ob += h * s_spnew[k];
            }
            s_d[tid] = s_post[tid] - s_spold[tid];
            s_e[tid] = y[tid * T_STEPS + t] - ob;
            if (blockIdx.x == 0) {
                g_m1x[cur][tid] = s_m1x[tid];
                g_m1y[cur][tid] = my;
                g_spp[cur][tid] = s_spnew[tid];
            }
        }
        __syncthreads();
        if (tid == 0) {
            float nd = 0.f, ne = 0.f;
#pragma unroll
            for (int k = 0; k < 16; ++k) { nd += s_d[k] * s_d[k]; ne += s_e[k] * s_e[k]; }
            s_nrm[0] = fmaxf(sqrtf(nd), 1e-12f);
            s_nrm[1] = fmaxf(sqrtf(ne), 1e-12f);
        }
        __syncthreads();
        if (tid < 32)
            s_kin[tid] = (tid < 16) ? s_d[tid] / s_nrm[0] : s_e[tid - 16] / s_nrm[1];
        __syncthreads();

        // l1 = relu(W1 @ kin + b1): one warp per row
        if (wid < H1D) {
            float v = W1[wid * 32 + lane] * s_kin[lane];
            v = wredsum(v);
            if (lane == 0) g_l1[wid] = fmaxf(v + b1[wid], 0.0f);
        }
        ++lg; gsync(lg);

        // ================= Phase B1: balanced full-row partial dots =========
        {
            const float*  hold = g_hbuf[cur];
            const float4* l1v  = (const float4*)g_l1;
            const float4* hv   = (const float4*)hold;
            for (int u = u_first; u < 2 * NROW && cost_start(u) < c1; ++u) {
                if (u < NROW) {
                    // Wih row u (fp32): dot with l1 -- identical order to r7
                    const float4* w = (const float4*)(Wih + (size_t)u * H1D);
                    float acc = 0.f;
#pragma unroll 4
                    for (int k = lane; k < H1D / 4; k += 32) {
                        float4 a = w[k]; float4 x = l1v[k];
                        acc += a.x * x.x + a.y * x.y + a.z * x.z + a.w * x.w;
                    }
                    acc = wredsum(acc);
                    if (lane == 0) __stcg(&g_pih[u], acc);
                } else {
                    // Whh row r (int24): dot with h -- identical order to r7
                    const int r = u - NROW;
                    const int g = r / HIDD, j = r % HIDD;
                    const size_t qrow = ((size_t)j * 3 + g) * HIDD;
                    const uint4* hp = (const uint4*)(Whh_hi + qrow);   // 640
                    const uint2* lp = (const uint2*)(Whh_lo + qrow);
                    float acc = 0.f;
#pragma unroll 2
                    for (int k = lane; k < HIDD / 8; k += 32) {
                        float4 x0 = hv[2 * k], x1 = hv[2 * k + 1];
                        acc += dec8(hp[k], lp[k], x0, x1);
                    }
                    acc = wredsum(acc);
                    if (lane == 0) __stcg(&g_phh[r], acc);
                }
            }
        }
        ++lg; gsync(lg);

        // ================= Phase B2: gate combine (lane-parallel) ===========
        if (wid < 160) {
            const int j = wid * 32 + lane;       // 0..5119
            const float* hold = g_hbuf[cur];
            float*       hnew = g_hbuf[prev];
            float ir  = __ldcg(&g_pih[j]);
            float iz  = __ldcg(&g_pih[HIDD + j]);
            float in_ = __ldcg(&g_pih[2 * HIDD + j]);
            float hr  = __ldcg(&g_phh[j])            * S_hh[j * 3 + 0];
            float hz  = __ldcg(&g_phh[HIDD + j])     * S_hh[j * 3 + 1];
            float hn  = __ldcg(&g_phh[2 * HIDD + j]) * S_hh[j * 3 + 2];
            float r  = sigmoidf_(ir + bih[j]            + hr + bhh[j]);
            float z  = sigmoidf_(iz + bih[HIDD + j]     + hz + bhh[HIDD + j]);
            float nn = tanhf   (in_ + bih[2 * HIDD + j] + r * (hn + bhh[2 * HIDD + j]));
            hnew[j] = (1.0f - z) * nn + z * hold[j];
        }
        ++lg; gsync(lg);

        // ================= Phase C: l2 = relu(W2 @ h_new + b2) ==============
        if (wid < H2D) {
            const float4* hvn = (const float4*)g_hbuf[prev];
            const float4* w   = (const float4*)(W2 + (size_t)wid * HIDD);
            float acc = 0.f;
#pragma unroll 4
            for (int k = lane; k < HIDD / 4; k += 32) {
                float4 a = w[k]; float4 x = hvn[k];
                acc += a.x * x.x + a.y * x.y + a.z * x.z + a.w * x.w;
            }
            acc = wredsum(acc);
            if (lane == 0) g_l2[wid] = fmaxf(acc + b2[wid], 0.0f);
        }
        ++lg; gsync(lg);

        // ================= Phase D: KG = W3 @ l2 + b3 =======================
        if (wid < MDIM * NDIM) {
            const float4* lv = (const float4*)g_l2;
            const float4* w  = (const float4*)(W3 + (size_t)wid * H2D);
            float acc = 0.f;
#pragma unroll
            for (int k = lane; k < H2D / 4; k += 32) {
                float4 a = w[k]; float4 x = lv[k];
                acc += a.x * x.x + a.y * x.y + a.z * x.z + a.w * x.w;
            }
            acc = wredsum(acc);
            if (lane == 0) g_KG[wid] = acc + b3[wid];
        }
        ++lg; gsync(lg);
    }

    // ---- final output column (post update of step T-1) ----
    if (blockIdx.x == 0 && tid < 16) {
        const int pl = (T_STEPS - 1) & 1;
        float acc = g_m1x[pl][tid];
#pragma unroll
        for (int k = 0; k < 16; ++k)
            acc += g_KG[tid * 16 + k] * (y[k * T_STEPS + (T_STEPS - 1)] - g_m1y[pl][k]);
        out[tid * T_STEPS + (T_STEPS - 1)] = acc;
    }
}

extern "C" void kernel_launch(void* const* d_in, const int* in_sizes, int n_in,
                              void* d_out, int out_size) {
    const float* y    = (const float*)d_in[0];
    const float* F    = (const float*)d_in[1];
    const float* Hm   = (const float*)d_in[2];
    const float* m1_0 = (const float*)d_in[3];
    const float* h0   = (const float*)d_in[4];
    const float* W1   = (const float*)d_in[5];
    const float* b1   = (const float*)d_in[6];
    const float* Wih  = (const float*)d_in[7];
    const float* bih  = (const float*)d_in[8];
    const float* Whh  = (const float*)d_in[9];
    const float* bhh  = (const float*)d_in[10];
    const float* W2   = (const float*)d_in[11];
    const float* b2   = (const float*)d_in[12];
    const float* W3   = (const float*)d_in[13];
    const float* b3   = (const float*)d_in[14];
    float* out = (float*)d_out;

    init_kernel<<<20, 256>>>(h0);
    knet_kernel<<<NBLK, NTHR>>>(y, F, Hm, m1_0, W1, b1, Wih, bih, Whh,
                                bhh, W2, b2, W3, b3, out);
}

// round 15
// speedup vs baseline: 1.5452x; 1.2198x over previous
#include <cuda_runtime.h>
#include <math.h>

#define T_STEPS 100
#define MDIM 16
#define NDIM 16
#define H1D  2560      // W1 rows, GRU input dim
#define H2D  1024
#define HIDD 5120
#define NBLK 320
#define NTHR 256
#define NWARP (NBLK * (NTHR/32))   // 2560 warps

// ---------------- persistent device state ----------------
__device__ float g_l1[H1D];
__device__ float g_hbuf[2][HIDD];
__device__ float g_l2[H2D];
__device__ float g_KG[MDIM * NDIM];
__device__ float g_m1x[2][MDIM];
__device__ float g_m1y[2][NDIM];
__device__ float g_spp[2][MDIM];
__device__ unsigned g_count;
__device__ volatile unsigned g_gen;

// Whh quantized + BIASED: stored hi = (s16 ^ 0x8000), lo = (s8 ^ 0x80)
// w ~= S_hh[j*3+g] * (s16 + s8/256); row = j*3+g   (~236 MB statics)
__device__ unsigned short Whh_hi[(size_t)HIDD * 3 * HIDD];   // 157.3 MB
__device__ unsigned char  Whh_lo[(size_t)HIDD * 3 * HIDD];   //  78.6 MB
__device__ float          S_hh[HIDD * 3];

// ---------------- quantize + repack Whh (biased storage) ----------------
__global__ void quant_hh_kernel(const float* __restrict__ src) {
    const int j = blockIdx.x, g = blockIdx.y;
    const float4* s = (const float4*)(src + ((size_t)g * HIDD + j) * HIDD); // 1280 float4
    const size_t drow = ((size_t)j * 3 + g) * HIDD;
    __shared__ float red[256];
    float mx = 0.f;
    for (int k = threadIdx.x; k < HIDD / 4; k += 256) {
        float4 v = s[k];
        mx = fmaxf(mx, fmaxf(fmaxf(fabsf(v.x), fabsf(v.y)), fmaxf(fabsf(v.z), fabsf(v.w))));
    }
    red[threadIdx.x] = mx;
    __syncthreads();
    for (int o = 128; o > 0; o >>= 1) {
        if (threadIdx.x < o) red[threadIdx.x] = fmaxf(red[threadIdx.x], red[threadIdx.x + o]);
        __syncthreads();
    }
    float m = red[0];
    float sc  = (m > 0.f) ? m / 32767.0f : 1.0f;
    float inv = (m > 0.f) ? 32767.0f / m : 0.0f;
    if (threadIdx.x == 0) S_hh[j * 3 + g] = sc;

    uint4* hrow = (uint4*)(Whh_hi + drow);   // 640 uint4 (8 biased u16 each)
    uint2* lrow = (uint2*)(Whh_lo + drow);   // 640 uint2 (8 biased u8 each)
    for (int k8 = threadIdx.x; k8 < HIDD / 8; k8 += 256) {
        float4 a = s[2 * k8], b = s[2 * k8 + 1];
        float f[8] = {a.x, a.y, a.z, a.w, b.x, b.y, b.z, b.w};
        unsigned hs[8], ls[8];
#pragma unroll
        for (int i = 0; i < 8; ++i) {
            float ff = f[i] * inv;
            float hq = rintf(ff);
            float d  = (ff - hq) * 256.0f;
            float lq = fminf(fmaxf(rintf(d), -128.0f), 127.0f);
            hs[i] = ((unsigned)(unsigned short)(short)hq) ^ 0x8000u;   // biased
            ls[i] = ((unsigned)(unsigned char)(signed char)lq) ^ 0x80u; // biased
        }
        uint4 hv;
        hv.x = hs[0] | (hs[1] << 16);
        hv.y = hs[2] | (hs[3] << 16);
        hv.z = hs[4] | (hs[5] << 16);
        hv.w = hs[6] | (hs[7] << 16);
        uint2 lv;
        lv.x = ls[0] | (ls[1] << 8) | (ls[2] << 16) | (ls[3] << 24);
        lv.y = ls[4] | (ls[5] << 8) | (ls[6] << 16) | (ls[7] << 24);
        hrow[k8] = hv;
        lrow[k8] = lv;
    }
}

__global__ void init_kernel(const float* __restrict__ h0) {
    int i = blockIdx.x * blockDim.x + threadIdx.x;
    if (i < HIDD) g_hbuf[0][i] = h0[i];
    if (i == 0) { g_count = 0; g_gen = 0; }
}

// ---------------- grid-wide spin barrier (r1/r7-proven) ----------------
__device__ __forceinline__ void gsync(unsigned target) {
    __syncthreads();
    if (threadIdx.x == 0) {
        __threadfence();
        if (atomicAdd(&g_count, 1u) == gridDim.x - 1) {
            atomicExch(&g_count, 0u);
            __threadfence();
            g_gen = target;
        } else {
            while (g_gen < target) { __nanosleep(64); }
        }
        __threadfence();
    }
    __syncthreads();
}

__device__ __forceinline__ float wredsum(float v) {
#pragma unroll
    for (int o = 16; o > 0; o >>= 1) v += __shfl_xor_sync(0xffffffffu, v, o);
    return v;
}

__device__ __forceinline__ float sigmoidf_(float x) {
    return 1.0f / (1.0f + __expf(-x));
}

// ---- I2F-free decode: PRMT magic-number + exact subtract ----
// hi: result 0x4B00'xxxx as float = 2^23 + u16; minus (2^23 + 2^15) = s16  (exact)
// lo: result 0x4B00'00xx as float = 2^23 + u8;  minus (2^23 + 2^7)  = s8   (exact)
__device__ __forceinline__ float dec8p(uint4 h, uint2 l, float4 x0, float4 x1) {
    const float R  = 0.00390625f;     // 1/256
    const float CH = 8421376.0f;      // 2^23 + 2^15
    const float CL = 8388736.0f;      // 2^23 + 2^7
    float h0 = __uint_as_float(__byte_perm(h.x, 0x4B00u, 0x5410)) - CH;
    float h1 = __uint_as_float(__byte_perm(h.x, 0x4B00u, 0x5432)) - CH;
    float h2 = __uint_as_float(__byte_perm(h.y, 0x4B00u, 0x5410)) - CH;
    float h3 = __uint_as_float(__byte_perm(h.y, 0x4B00u, 0x5432)) - CH;
    float h4 = __uint_as_float(__byte_perm(h.z, 0x4B00u, 0x5410)) - CH;
    float h5 = __uint_as_float(__byte_perm(h.z, 0x4B00u, 0x5432)) - CH;
    float h6 = __uint_as_float(__byte_perm(h.w, 0x4B00u, 0x5410)) - CH;
    float h7 = __uint_as_float(__byte_perm(h.w, 0x4B00u, 0x5432)) - CH;
    float l0 = __uint_as_float(__byte_perm(l.x, 0x4B00u, 0x5440)) - CL;
    float l1 = __uint_as_float(__byte_perm(l.x, 0x4B00u, 0x5441)) - CL;
    float l2 = __uint_as_float(__byte_perm(l.x, 0x4B00u, 0x5442)) - CL;
    float l3 = __uint_as_float(__byte_perm(l.x, 0x4B00u, 0x5443)) - CL;
    float l4 = __uint_as_float(__byte_perm(l.y, 0x4B00u, 0x5440)) - CL;
    float l5 = __uint_as_float(__byte_perm(l.y, 0x4B00u, 0x5441)) - CL;
    float l6 = __uint_as_float(__byte_perm(l.y, 0x4B00u, 0x5442)) - CL;
    float l7 = __uint_as_float(__byte_perm(l.y, 0x4B00u, 0x5443)) - CL;
    // w_i = h_i + l_i/256  (exact; bit-identical to the r7 I2F decode)
    float w0 = fmaf(l0, R, h0);
    float w1 = fmaf(l1, R, h1);
    float w2 = fmaf(l2, R, h2);
    float w3 = fmaf(l3, R, h3);
    float w4 = fmaf(l4, R, h4);
    float w5 = fmaf(l5, R, h5);
    float w6 = fmaf(l6, R, h6);
    float w7 = fmaf(l7, R, h7);
    float acc = w0 * x0.x;
    acc = fmaf(w1, x0.y, acc);
    acc = fmaf(w2, x0.z, acc);
    acc = fmaf(w3, x0.w, acc);
    acc = fmaf(w4, x1.x, acc);
    acc = fmaf(w5, x1.y, acc);
    acc = fmaf(w6, x1.z, acc);
    acc = fmaf(w7, x1.w, acc);
    return acc;
}

__global__ void __launch_bounds__(NTHR, 3)
knet_kernel(const float* __restrict__ y,  const float* __restrict__ F,
            const float* __restrict__ Hm, const float* __restrict__ m1_0,
            const float* __restrict__ W1, const float* __restrict__ b1,
            const float* __restrict__ Wih, const float* __restrict__ bih,
            const float* __restrict__ bhh,
            const float* __restrict__ W2, const float* __restrict__ b2,
            const float* __restrict__ W3, const float* __restrict__ b3,
            float* __restrict__ out)
{
    const int tid  = threadIdx.x;
    const int lane = tid & 31;
    const int wid  = blockIdx.x * (NTHR / 32) + (tid >> 5);  // 0..2559
    unsigned lg = 0;

    __shared__ float s_post[16], s_spold[16], s_m1x[16], s_spnew[16];
    __shared__ float s_d[16], s_e[16], s_kin[32], s_nrm[2];

    for (int t = 0; t < T_STEPS; ++t) {
        const int cur = t & 1, prev = cur ^ 1;

        // ================= Phase A: post update + state + kin + l1 ==========
        if (tid < 16) {
            float p, sp;
            if (t == 0) {
                p = m1_0[tid]; sp = m1_0[tid];
            } else {
                float acc = g_m1x[prev][tid];
#pragma unroll
                for (int k = 0; k < 16; ++k)
                    acc += g_KG[tid * 16 + k] * (y[k * T_STEPS + (t - 1)] - g_m1y[prev][k]);
                p  = acc;
                sp = g_spp[prev][tid];
                if (blockIdx.x == 0) out[tid * T_STEPS + (t - 1)] = p;
            }
            s_post[tid] = p; s_spold[tid] = sp;
        }
        __syncthreads();
        if (tid < 16) {
            float mx = 0.f, sn = 0.f;
#pragma unroll
            for (int k = 0; k < 16; ++k) {
                float f = F[tid * 16 + k];
                mx += f * s_post[k];
                sn += f * s_spold[k];
            }
            s_m1x[tid] = mx; s_spnew[tid] = sn;
        }
        __syncthreads();
        if (tid < 16) {
            float my = 0.f, ob = 0.f;
#pragma unroll
            for (int k = 0; k < 16; ++k) {
                float h = Hm[tid * 16 + k];
                my += h * s_m1x[k];
                ob += h * s_spnew[k];
            }
            s_d[tid] = s_post[tid] - s_spold[tid];
            s_e[tid] = y[tid * T_STEPS + t] - ob;
            if (blockIdx.x == 0) {
                g_m1x[cur][tid] = s_m1x[tid];
                g_m1y[cur][tid] = my;
                g_spp[cur][tid] = s_spnew[tid];
            }
        }
        __syncthreads();
        if (tid == 0) {
            float nd = 0.f, ne = 0.f;
#pragma unroll
            for (int k = 0; k < 16; ++k) { nd += s_d[k] * s_d[k]; ne += s_e[k] * s_e[k]; }
            s_nrm[0] = fmaxf(sqrtf(nd), 1e-12f);
            s_nrm[1] = fmaxf(sqrtf(ne), 1e-12f);
        }
        __syncthreads();
        if (tid < 32)
            s_kin[tid] = (tid < 16) ? s_d[tid] / s_nrm[0] : s_e[tid - 16] / s_nrm[1];
        __syncthreads();

        // l1 = relu(W1 @ kin + b1): one warp per row (2560 warps == 2560 rows)
        {
            float v = W1[wid * 32 + lane] * s_kin[lane];
            v = wredsum(v);
            if (lane == 0) g_l1[wid] = fmaxf(v + b1[wid], 0.0f);
        }
        ++lg; gsync(lg);

        // ================= Phase B: fused GRU GEMV ==========================
        //   Wih: fp32 (r1-identical); Whh: int24, PRMT magic decode
        {
            const float*  hold = g_hbuf[cur];     // t=0 -> slot 0 holds h0
            float*        hnew = g_hbuf[prev];
            const float4* l1v  = (const float4*)g_l1;
            const float4* hv   = (const float4*)hold;
#pragma unroll
            for (int e = 0; e < 2; ++e) {
                const int j = wid + e * 2560;     // hidden element index
                float ar = 0.f, az = 0.f, an = 0.f;
                float br = 0.f, bz = 0.f, bn = 0.f;
                const float4* wr = (const float4*)(Wih + (size_t)(0 * HIDD + j) * H1D);
                const float4* wz = (const float4*)(Wih + (size_t)(1 * HIDD + j) * H1D);
                const float4* wn = (const float4*)(Wih + (size_t)(2 * HIDD + j) * H1D);
#pragma unroll 4
                for (int k = lane; k < H1D / 4; k += 32) {
                    float4 x = l1v[k];
                    float4 a = wr[k]; ar += a.x * x.x + a.y * x.y + a.z * x.z + a.w * x.w;
                    float4 b = wz[k]; az += b.x * x.x + b.y * x.y + b.z * x.z + b.w * x.w;
                    float4 c = wn[k]; an += c.x * x.x + c.y * x.y + c.z * x.z + c.w * x.w;
                }
                const uint4* hi_h = (const uint4*)(Whh_hi + (size_t)j * 3 * HIDD);  // 640 uint4/gate
                const uint2* lo_h = (const uint2*)(Whh_lo + (size_t)j * 3 * HIDD);  // 640 uint2/gate
#pragma unroll 2
                for (int k = lane; k < HIDD / 8; k += 32) {
                    float4 x0 = hv[2 * k], x1 = hv[2 * k + 1];
                    br += dec8p(hi_h[k],        lo_h[k],        x0, x1);
                    bz += dec8p(hi_h[640 + k],  lo_h[640 + k],  x0, x1);
                    bn += dec8p(hi_h[1280 + k], lo_h[1280 + k], x0, x1);
                }
                ar = wredsum(ar); az = wredsum(az); an = wredsum(an);
                br = wredsum(br); bz = wredsum(bz); bn = wredsum(bn);
                if (lane == 0) {
                    float hr = br * S_hh[j * 3 + 0];
                    float hz = bz * S_hh[j * 3 + 1];
                    float hn = bn * S_hh[j * 3 + 2];
                    float r  = sigmoidf_(ar + bih[j]            + hr + bhh[j]);
                    float z  = sigmoidf_(az + bih[HIDD + j]     + hz + bhh[HIDD + j]);
                    float nn = tanhf   (an + bih[2 * HIDD + j] + r * (hn + bhh[2 * HIDD + j]));
                    hnew[j] = (1.0f - z) * nn + z * hold[j];
                }
            }
        }
        ++lg; gsync(lg);

        // ================= Phase C: l2 = relu(W2 @ h_new + b2) ==============
        if (wid < H2D) {
            const float4* hvn = (const float4*)g_hbuf[prev];   // h_new
            const float4* w   = (const float4*)(W2 + (size_t)wid * HIDD);
            float acc = 0.f;
#pragma unroll 4
            for (int k = lane; k < HIDD / 4; k += 32) {
                float4 a = w[k]; float4 x = hvn[k];
                acc += a.x * x.x + a.y * x.y + a.z * x.z + a.w * x.w;
            }
            acc = wredsum(acc);
            if (lane == 0) g_l2[wid] = fmaxf(acc + b2[wid], 0.0f);
        }
        ++lg; gsync(lg);

        // ================= Phase D: KG = W3 @ l2 + b3 =======================
        if (wid < MDIM * NDIM) {
            const float4* lv = (const float4*)g_l2;
            const float4* w  = (const float4*)(W3 + (size_t)wid * H2D);
            float acc = 0.f;
#pragma unroll
            for (int k = lane; k < H2D / 4; k += 32) {
                float4 a = w[k]; float4 x = lv[k];
                acc += a.x * x.x + a.y * x.y + a.z * x.z + a.w * x.w;
            }
            acc = wredsum(acc);
            if (lane == 0) g_KG[wid] = acc + b3[wid];
        }
        ++lg; gsync(lg);
    }

    // ---- final output column (post update of step T-1) ----
    if (blockIdx.x == 0 && tid < 16) {
        const int pl = (T_STEPS - 1) & 1;
        float acc = g_m1x[pl][tid];
#pragma unroll
        for (int k = 0; k < 16; ++k)
            acc += g_KG[tid * 16 + k] * (y[k * T_STEPS + (T_STEPS - 1)] - g_m1y[pl][k]);
        out[tid * T_STEPS + (T_STEPS - 1)] = acc;
    }
}

extern "C" void kernel_launch(void* const* d_in, const int* in_sizes, int n_in,
                              void* d_out, int out_size) {
    const float* y    = (const float*)d_in[0];
    const float* F    = (const float*)d_in[1];
    const float* Hm   = (const float*)d_in[2];
    const float* m1_0 = (const float*)d_in[3];
    const float* h0   = (const float*)d_in[4];
    const float* W1   = (const float*)d_in[5];
    const float* b1   = (const float*)d_in[6];
    const float* Wih  = (const float*)d_in[7];
    const float* bih  = (const float*)d_in[8];
    const float* Whh  = (const float*)d_in[9];
    const float* bhh  = (const float*)d_in[10];
    const float* W2   = (const float*)d_in[11];
    const float* b2   = (const float*)d_in[12];
    const float* W3   = (const float*)d_in[13];
    const float* b3   = (const float*)d_in[14];
    float* out = (float*)d_out;

    quant_hh_kernel<<<dim3(HIDD, 3), 256>>>(Whh);
    init_kernel<<<20, 256>>>(h0);
    knet_kernel<<<NBLK, NTHR>>>(y, F, Hm, m1_0, W1, b1, Wih, bih,
                                bhh, W2, b2, W3, b3, out);
}